// round 7
// baseline (speedup 1.0000x reference)
#include <cuda_runtime.h>
#include <cuda_bf16.h>
#include <cstdint>

// Problem shapes (fixed for this dataset entry)
constexpr int B = 4;
constexpr int S = 4096;
constexpr int D = 2048;

constexpr int HALO = 8;    // recurrence depth N_BLANKS
constexpr int LEAD = 4;    // load prefetch distance (iterations)

constexpr int TTM    = 32;                // t-tile per work unit
constexpr int DSPLIT = 4;                 // D quarters per tile
constexpr int TB     = D / 4 / DSPLIT;    // 128 threads, one float4 lane each

constexpr int NT     = (S / TTM) * B * DSPLIT;  // 2048 tiles
constexpr int GRID   = 1480;                    // 148 SMs x 10 blocks: one wave

// ---------------------------------------------------------------------------
// Persistent fused kernel.
//  Per tile:
//   Warps 0-1: warp-shuffle weight DP
//     w^k[t][j] = w^{k-1}[t][j] + p[t-k] * w^{k-1}[t-1][j-1],  w_0 == 1 implicit
//     p[t] = (x[t] >= 16) && (x[t+1] < 16), zero outside [0, S-1)
//     lane = t position; influence moves 1 lane per level, so lanes >= 8 exact.
//     warp0: t in [T0-8, T0+24) -> i = 0..23 ; warp1: t in [T0+16, T0+48) -> i = 24..31
//     Ballot-packed "slow path" bits: sany[0] = i0..23, sany[1] = i24..31.
//   Warps 2-3: stage gather byte-offsets.
//  Stream: out[t] = e[t] + sum_j w_j(t) * e[t-j]
// ---------------------------------------------------------------------------
__global__ __launch_bounds__(TB, 10)
void fused_kernel(const int* __restrict__ x,
                  const float* __restrict__ emb,
                  float* __restrict__ out)
{
    const int tid  = threadIdx.x;
    const int wid  = tid >> 5;
    const int lane = tid & 31;

    __shared__ alignas(16) int sidx[TTM + HALO + LEAD];  // 44 ints, byte offsets
    __shared__ float    sw[TTM][HALO];                   // weights w_1..w_8 per t
    __shared__ unsigned sflag[TTM];                      // detailed nonzero masks
    __shared__ unsigned sany[2];                         // packed any-bits

    for (int tile = blockIdx.x; tile < NT; tile += GRID) {
        const int tt = tile & (S / TTM - 1);
        const int b  = (tile >> 7) & (B - 1);
        const int z  = tile >> 9;
        const int T0 = tt * TTM;
        const int d4 = tid + z * TB;                     // float4 index within D

        if (wid >= 2) {
            // ---- stage gather byte-offsets for t = T0-HALO+i (clamped) ----
            const int i = tid - 64;
            if (i < TTM + HALO + LEAD) {
                int t = T0 - HALO + i;
                t = max(0, min(t, S - 1));
                sidx[i] = x[b * S + t] * (D * (int)sizeof(float));
            }
        } else {
            // ---- warp-shuffle weight DP ----
            const int base = (wid == 0) ? (T0 - HALO) : (T0 + 2 * HALO);
            const int t    = base + lane;

            int xs[9];                                   // x[t-8 .. t]
#pragma unroll
            for (int i = 0; i < 9; i++) {
                int s = t - 8 + i;
                s = max(0, min(s, S - 1));
                xs[i] = x[b * S + s];
            }
            unsigned pm = 0;                             // bit k: p[t-k] != 0
#pragma unroll
            for (int k = 1; k <= 8; k++) {
                int s = t - k;
                if (s >= 0 && s + 1 < S && xs[8 - k] >= 16 && xs[9 - k] < 16)
                    pm |= (1u << k);
            }

            float wj[HALO];
#pragma unroll
            for (int j = 0; j < HALO; j++) wj[j] = 0.0f;

#pragma unroll
            for (int k = 1; k <= 8; k++) {
                const float pv = (pm >> k) & 1u ? 1.0f : 0.0f;
                float nb[HALO - 1];
#pragma unroll
                for (int j = 0; j < HALO - 1; j++)
                    nb[j] = __shfl_up_sync(0xFFFFFFFFu, wj[j], 1);
                float nb0 = 1.0f;
                if (lane == 0) {
                    nb0 = 0.0f;
#pragma unroll
                    for (int j = 0; j < HALO - 1; j++) nb[j] = 0.0f;
                }
                wj[0] = fmaf(pv, nb0, wj[0]);
#pragma unroll
                for (int j = 1; j < HALO; j++) wj[j] = fmaf(pv, nb[j - 1], wj[j]);
            }

            const int i = t - T0;
            unsigned m = 0;
#pragma unroll
            for (int j = 0; j < HALO; j++)
                if (wj[j] != 0.0f) m |= (1u << (j + 1));

            const unsigned bal = __ballot_sync(0xFFFFFFFFu, m != 0);
            if (lane >= HALO && i >= 0 && i < TTM) {
#pragma unroll
                for (int j = 0; j < HALO; j++) sw[i][j] = wj[j];
                sflag[i] = m;
            }
            if (lane == HALO) {
                if (wid == 0) sany[0] = (bal >> 8);          // i 0..23 -> bits 0..23
                else          sany[1] = (bal >> 8) & 0xFFu;  // i 24..31 -> bits 0..7
            }
        }
        __syncthreads();

        const unsigned any = sany[0] | (sany[1] << 24);      // bit i: slow path at i

        // ---- main streaming loop: out[t] = e[t] + sum_j w_j(t) * e[t-j] ----
        const char* embp = (const char*)emb + (size_t)d4 * 16;
        float*      outp = out + ((size_t)(b * S + T0)) * D + (size_t)d4 * 4;

        float4 pipe[LEAD];
        {
            const int4 fi = *reinterpret_cast<const int4*>(&sidx[HALO]);  // byte 32, aligned
            pipe[0] = *reinterpret_cast<const float4*>(embp + fi.x);
            pipe[1] = *reinterpret_cast<const float4*>(embp + fi.y);
            pipe[2] = *reinterpret_cast<const float4*>(embp + fi.z);
            pipe[3] = *reinterpret_cast<const float4*>(embp + fi.w);
        }

        for (int g = 0; g < TTM / LEAD; g++) {
            // prefetch indices for i = 4g..4g+3: sidx[HALO+LEAD+4g ..+3], 16B aligned
            const int4 ni = *reinterpret_cast<const int4*>(&sidx[HALO + LEAD + 4 * g]);
            const int nidx[4] = {ni.x, ni.y, ni.z, ni.w};
#pragma unroll
            for (int u = 0; u < LEAD; u++) {
                const int i = g * LEAD + u;
                float4 c = pipe[u];
                pipe[u] = *reinterpret_cast<const float4*>(embp + nidx[u]);

                if ((any >> i) & 1u) {
                    const unsigned m = sflag[i];
#pragma unroll
                    for (int j = 1; j <= HALO; j++) {
                        if (m & (1u << j)) {
                            const float w = sw[i][j - 1];
                            const float4 h = *reinterpret_cast<const float4*>(
                                embp + sidx[HALO + i - j]);
                            c.x = fmaf(h.x, w, c.x);
                            c.y = fmaf(h.y, w, c.y);
                            c.z = fmaf(h.z, w, c.z);
                            c.w = fmaf(h.w, w, c.w);
                        }
                    }
                }
                // streaming store: evict-first, keep emb table resident in L2
                __stcs(reinterpret_cast<float4*>(outp + (size_t)i * D), c);
            }
        }
        __syncthreads();   // protect smem before next tile's staging
    }
}

extern "C" void kernel_launch(void* const* d_in, const int* in_sizes, int n_in,
                              void* d_out, int out_size)
{
    const int*   x   = (const int*)d_in[0];
    const float* emb = (const float*)d_in[1];
    float*       out = (float*)d_out;

    fused_kernel<<<GRID, TB>>>(x, emb, out);
}